// round 6
// baseline (speedup 1.0000x reference)
#include <cuda_runtime.h>
#include <math.h>

namespace {
constexpr int B = 16, T = 100, N = 128, D = 3;
constexpr int FRAMES = B * T;                 // 1600
constexpr int NIT = 4;                        // consecutive frames per block
constexpr int BLOCKS = FRAMES / NIT;          // 400 persistent blocks
constexpr int FD = N * D;                     // 384 floats per frame
constexpr float MIN_DIST = 0.05f;
constexpr float R2 = MIN_DIST * MIN_DIST;     // 0.0025
constexpr float R2_GUARD = R2 + 1e-4f;        // slack for expansion error
constexpr int EXT = 192;                      // 128 + 64 wrap replica
}

__device__ float g_pen[BLOCKS];
__device__ float g_work[BLOCKS];
__device__ float g_stab[BLOCKS];
__device__ float g_ke0[BLOCKS];
__device__ float g_ke1[BLOCKS];
__device__ unsigned int g_count;              // zero-init; self-resetting

__global__ __launch_bounds__(256, 3) void fused_kernel(
    const float* __restrict__ traj,
    const float* __restrict__ vel,
    const float* __restrict__ frc,
    float* __restrict__ out)
{
    const int tid  = threadIdx.x;
    const int i    = tid & 127;        // row index
    const int half = tid >> 7;         // j-range half: 0 -> 1..32, 1 -> 33..64
    const int f0   = blockIdx.x * NIT;

    __shared__ __align__(16) float4 spos[EXT];   // (x,y,z,|p|^2)

    // staging map: this thread owns frame floats q0 = tid (always) and
    // q1 = 256 + tid (tid < 128 only)
    const bool has2 = (tid < 128);
    const int  q0 = tid, q1 = 256 + tid;
    const int  s0 = 4 * (q0 / 3) + (q0 % 3);
    const int  s1 = 4 * (q1 / 3) + (q1 % 3);
    float* sraw = reinterpret_cast<float*>(spos);

    // ---- prologue: load frame f0 positions into cur regs ----
    float c0 = traj[(size_t)f0 * FD + q0];
    float c1 = has2 ? traj[(size_t)f0 * FD + q1] : 0.f;

    float penacc = 0.f, wrkacc = 0.f, stabacc = 0.f, ke0acc = 0.f, ke1acc = 0.f;

    #pragma unroll 1
    for (int it = 0; it < NIT; ++it) {
        const int f = f0 + it;
        const int t = f % T;

        // ---- stage cur -> smem float4 slots ----
        __syncthreads();               // WAR: previous iteration done reading
        sraw[s0] = c0;
        if (has2) sraw[s1] = c1;
        __syncthreads();

        // ---- fill |p|^2 and wrap replica in one phase ----
        if (tid < 128) {
            float4 v = spos[tid];
            float w = v.x * v.x + v.y * v.y + v.z * v.z;
            spos[tid].w = w;
            if (tid < 64) spos[128 + tid] = make_float4(v.x, v.y, v.z, w);
        }

        // ---- issue prefetch: next frame positions + this frame forces ----
        float n0 = 0.f, n1 = 0.f, fr0 = 0.f, fr1 = 0.f;
        const bool havenext = (f + 1 < FRAMES);
        if (havenext) {
            n0 = traj[(size_t)(f + 1) * FD + q0];
            if (has2) n1 = traj[(size_t)(f + 1) * FD + q1];
        }
        if (t < T - 1) {
            fr0 = frc[(size_t)f * FD + q0];
            if (has2) fr1 = frc[(size_t)f * FD + q1];
        }
        __syncthreads();               // smem frame ready

        // ---- penetration mainloop (latency of prefetch hidden behind it) ----
        const float4 me  = spos[i];
        const float  mw  = me.w;
        const float  m2x = -2.0f * me.x;
        const float  m2y = -2.0f * me.y;
        const float  m2z = -2.0f * me.z;
        const int jbase = 1 + 32 * half;
        const float4* base = spos + i + jbase;

        float accA = 1e30f, accB = 1e30f;
        #pragma unroll
        for (int jj = 0; jj < 32; ++jj) {
            float4 qq = base[jj];
            float d2 = mw + qq.w;
            d2 = fmaf(m2x, qq.x, d2);
            d2 = fmaf(m2y, qq.y, d2);
            d2 = fmaf(m2z, qq.z, d2);
            if (jj & 1) accB = fminf(accB, d2);
            else        accA = fminf(accA, d2);
        }
        if (fminf(accA, accB) < R2_GUARD) {     // rare exact slow path
            for (int jj = 0; jj < 32; ++jj) {
                float4 qq = base[jj];
                float dx = me.x - qq.x, dy = me.y - qq.y, dz = me.z - qq.z;
                float e2 = dx * dx + dy * dy + dz * dz;
                if (e2 < R2) {
                    float c = MIN_DIST - sqrtf(e2);
                    penacc += (jbase + jj == 64) ? 0.5f * c : c;
                }
            }
        }

        // ---- stability / kinetic (boundary frames only) ----
        if (tid < 128 && (t == 0 || t >= T - 5)) {
            const float* pv = vel + (size_t)f * FD;
            float vx = pv[3 * i], vy = pv[3 * i + 1], vz = pv[3 * i + 2];
            float v2 = vx * vx + vy * vy + vz * vz;
            if (t >= T - 5) {
                stabacc += sqrtf(v2);
                if (t == T - 1) ke1acc += 0.5f * v2;
            } else {
                ke0acc += 0.5f * v2;
            }
        }

        // ---- work term from pipeline registers ----
        if (t < T - 1) {
            wrkacc += fr0 * (n0 - c0);
            if (has2) wrkacc += fr1 * (n1 - c1);
        }
        c0 = n0; c1 = n1;
    }

    // ---- block reduction of 5 accumulators ----
    #pragma unroll
    for (int off = 16; off > 0; off >>= 1) {
        penacc  += __shfl_down_sync(0xffffffffu, penacc,  off);
        wrkacc  += __shfl_down_sync(0xffffffffu, wrkacc,  off);
        stabacc += __shfl_down_sync(0xffffffffu, stabacc, off);
        ke0acc  += __shfl_down_sync(0xffffffffu, ke0acc,  off);
        ke1acc  += __shfl_down_sync(0xffffffffu, ke1acc,  off);
    }
    __shared__ float sm[8][5];
    if ((tid & 31) == 0) {
        int w = tid >> 5;
        sm[w][0] = penacc; sm[w][1] = wrkacc; sm[w][2] = stabacc;
        sm[w][3] = ke0acc; sm[w][4] = ke1acc;
    }
    __syncthreads();
    if (tid == 0) {
        float sp = 0.f, sw = 0.f, ss = 0.f, s0v = 0.f, s1v = 0.f;
        #pragma unroll
        for (int w = 0; w < 8; ++w) {
            sp += sm[w][0]; sw += sm[w][1]; ss += sm[w][2];
            s0v += sm[w][3]; s1v += sm[w][4];
        }
        g_pen[blockIdx.x]  = sp;
        g_work[blockIdx.x] = sw;
        g_stab[blockIdx.x] = ss;
        g_ke0[blockIdx.x]  = s0v;
        g_ke1[blockIdx.x]  = s1v;
    }

    // ---- last-arriving block: deterministic final reduction (2KB read) ----
    __threadfence();
    __shared__ int is_last;
    if (tid == 0) {
        unsigned int old = atomicAdd(&g_count, 1u);
        is_last = (old == BLOCKS - 1) ? 1 : 0;
    }
    __syncthreads();
    if (!is_last) return;

    float pen_s = 0.f, wrk_s = 0.f, stab_s = 0.f, k0 = 0.f, k1 = 0.f;
    #pragma unroll
    for (int q = tid; q < BLOCKS; q += 256) {
        pen_s  += g_pen[q];
        wrk_s  += g_work[q];
        stab_s += g_stab[q];
        k0     += g_ke0[q];
        k1     += g_ke1[q];
    }
    #pragma unroll
    for (int off = 16; off > 0; off >>= 1) {
        pen_s  += __shfl_down_sync(0xffffffffu, pen_s,  off);
        wrk_s  += __shfl_down_sync(0xffffffffu, wrk_s,  off);
        stab_s += __shfl_down_sync(0xffffffffu, stab_s, off);
        k0     += __shfl_down_sync(0xffffffffu, k0,     off);
        k1     += __shfl_down_sync(0xffffffffu, k1,     off);
    }
    if ((tid & 31) == 0) {
        int w = tid >> 5;
        sm[w][0] = pen_s; sm[w][1] = wrk_s; sm[w][2] = stab_s;
        sm[w][3] = k0;    sm[w][4] = k1;
    }
    __syncthreads();
    if (tid == 0) {
        float sp = 0.f, sw = 0.f, ss = 0.f, s0v = 0.f, s1v = 0.f;
        #pragma unroll
        for (int w = 0; w < 8; ++w) {
            sp += sm[w][0]; sw += sm[w][1]; ss += sm[w][2];
            s0v += sm[w][3]; s1v += sm[w][4];
        }
        const float pen_loss  = sp / (float)B / ((float)T * (float)N * (float)(N - 1) * 0.5f);
        const float work_mean = sw / (float)(B * (T - 1) * N);
        const float stab_mean = ss / (float)(B * 5 * N);
        const float ks        = s0v / (float)(B * N);
        const float ke_       = s1v / (float)(B * N);
        out[0] = 10.0f * pen_loss + stab_mean + 0.1f * fabsf(ke_ - ks - work_mean);
        g_count = 0u;   // self-reset for next graph replay
    }
}

extern "C" void kernel_launch(void* const* d_in, const int* in_sizes, int n_in,
                              void* d_out, int out_size)
{
    const float* traj = (const float*)d_in[0];
    const float* vel  = (const float*)d_in[1];
    const float* frc  = (const float*)d_in[2];

    fused_kernel<<<BLOCKS, 256>>>(traj, vel, frc, (float*)d_out);
}